// round 5
// baseline (speedup 1.0000x reference)
#include <cuda_runtime.h>
#include <cuda_bf16.h>
#include <math.h>
#include <stdint.h>

#define NB    4
#define NS    1024
#define NHID  1024
#define NHEADS 16
#define NKVH  4
#define DH    64
#define NE    8
#define NF    2048
#define NTOK  4096
#define QKVN  1536
#define GUN   4096

// ---------------- scratch (device globals, allocation-free) ----------------
__device__ float g_xn[NTOK * NHID];
__device__ __nv_bfloat16 g_xnh[NTOK * NHID];
__device__ __nv_bfloat16 g_xnl[NTOK * NHID];
__device__ float g_qkv[NTOK * QKVN];
__device__ __nv_bfloat16 g_atth[NTOK * NHID];
__device__ __nv_bfloat16 g_attl[NTOK * NHID];
__device__ float g_h[NTOK * NHID];
__device__ __nv_bfloat16 g_wqkvh[NHID * QKVN];
__device__ __nv_bfloat16 g_wqkvl[NHID * QKVN];
__device__ __nv_bfloat16 g_woh[NHID * NHID];
__device__ __nv_bfloat16 g_wol[NHID * NHID];
__device__ __nv_bfloat16 g_wguh[NE * NHID * GUN];
__device__ __nv_bfloat16 g_wgul[NE * NHID * GUN];
__device__ __nv_bfloat16 g_wdh[NE * NF * NHID];
__device__ __nv_bfloat16 g_wdl[NE * NF * NHID];
__device__ float g_GU[(size_t)NE * NTOK * GUN];
__device__ __nv_bfloat16 g_Gh[NE * NTOK * NF];
__device__ __nv_bfloat16 g_Gl[NE * NTOK * NF];
__device__ int   g_cnt[NE];
__device__ int   g_tok[NE * NTOK];
__device__ float g_wgt[NE * NTOK];

// ---------------- helpers ----------------
__device__ __forceinline__ uint32_t pack_hi2(float a, float b, uint32_t* lo) {
    __nv_bfloat16 ha = __float2bfloat16(a);
    __nv_bfloat16 hb = __float2bfloat16(b);
    __nv_bfloat16 la = __float2bfloat16(a - __bfloat162float(ha));
    __nv_bfloat16 lb = __float2bfloat16(b - __bfloat162float(hb));
    *lo = ((uint32_t)__bfloat16_as_ushort(lb) << 16) | (uint32_t)__bfloat16_as_ushort(la);
    return ((uint32_t)__bfloat16_as_ushort(hb) << 16) | (uint32_t)__bfloat16_as_ushort(ha);
}

__device__ __forceinline__ void ldsm4(uint32_t* r, uint32_t a) {
    asm volatile("ldmatrix.sync.aligned.m8n8.x4.shared.b16 {%0,%1,%2,%3}, [%4];\n"
        : "=r"(r[0]), "=r"(r[1]), "=r"(r[2]), "=r"(r[3]) : "r"(a));
}
__device__ __forceinline__ void ldsm4t(uint32_t* r, uint32_t a) {
    asm volatile("ldmatrix.sync.aligned.m8n8.x4.trans.shared.b16 {%0,%1,%2,%3}, [%4];\n"
        : "=r"(r[0]), "=r"(r[1]), "=r"(r[2]), "=r"(r[3]) : "r"(a));
}
__device__ __forceinline__ void mma16816(float* d, const uint32_t* a, uint32_t b0, uint32_t b1) {
    asm volatile("mma.sync.aligned.m16n8k16.row.col.f32.bf16.bf16.f32 "
        "{%0,%1,%2,%3},{%4,%5,%6,%7},{%8,%9},{%0,%1,%2,%3};\n"
        : "+f"(d[0]), "+f"(d[1]), "+f"(d[2]), "+f"(d[3])
        : "r"(a[0]), "r"(a[1]), "r"(a[2]), "r"(a[3]), "r"(b0), "r"(b1));
}
__device__ __forceinline__ void cpa16(uint32_t dst, const void* src, int sz) {
    asm volatile("cp.async.cg.shared.global [%0], [%1], 16, %2;\n"
        :: "r"(dst), "l"(src), "r"(sz));
}

// ---------------- fused RMSNorm + bf16 hi/lo split ----------------
// use_h=0: src = xext ; use_h=1: src = g_h
// write_xn=1: also store fp32 normalized row to g_xn (needed for router)
__global__ void rmsnorm_split_k(const float* __restrict__ xext, const float* __restrict__ w,
                                int use_h, int write_xn) {
    int t = blockIdx.x;
    const float* src = use_h ? (const float*)g_h : xext;
    const float4* xr = (const float4*)(src + (size_t)t * NHID);
    float4 v = xr[threadIdx.x];
    float ss = v.x*v.x + v.y*v.y + v.z*v.z + v.w*v.w;
    #pragma unroll
    for (int o = 16; o; o >>= 1) ss += __shfl_down_sync(0xffffffffu, ss, o);
    __shared__ float red[8];
    if ((threadIdx.x & 31) == 0) red[threadIdx.x >> 5] = ss;
    __syncthreads();
    if (threadIdx.x < 8) {
        float s = red[threadIdx.x];
        #pragma unroll
        for (int o = 4; o; o >>= 1) s += __shfl_down_sync(0xffu, s, o);
        if (threadIdx.x == 0) red[0] = s;
    }
    __syncthreads();
    float rs = rsqrtf(red[0] * (1.0f / NHID) + 1e-6f);
    float4 wv = ((const float4*)w)[threadIdx.x];
    float4 ov;
    ov.x = v.x * rs * wv.x;
    ov.y = v.y * rs * wv.y;
    ov.z = v.z * rs * wv.z;
    ov.w = v.w * rs * wv.w;
    if (write_xn) {
        ((float4*)(g_xn + (size_t)t * NHID))[threadIdx.x] = ov;
    }
    uint32_t l0, l1;
    uint32_t h0 = pack_hi2(ov.x, ov.y, &l0);
    uint32_t h1 = pack_hi2(ov.z, ov.w, &l1);
    uint32_t* ph = (uint32_t*)(g_xnh + (size_t)t * NHID) + threadIdx.x * 2;
    uint32_t* pl = (uint32_t*)(g_xnl + (size_t)t * NHID) + threadIdx.x * 2;
    ph[0] = h0;
    ph[1] = h1;
    pl[0] = l0;
    pl[1] = l1;
}

// ---------------- combined QKV weight split-pack ----------------
// dst packed columns [H][1536] = Wq | Wk | Wv
__global__ void split_pack_qkv_k(const float4* __restrict__ Wq, const float4* __restrict__ Wk,
                                 const float4* __restrict__ Wv) {
    int i = blockIdx.x * 256 + threadIdx.x;   // i indexes float4 groups of dst
    int el = i * 4;
    int r = el / QKVN;
    int c = el % QKVN;
    float4 v;
    if (c < 1024)      v = Wq[(r * 1024 + c) / 4];
    else if (c < 1280) v = Wk[(r * 256 + (c - 1024)) / 4];
    else               v = Wv[(r * 256 + (c - 1280)) / 4];
    uint32_t l0, l1;
    uint32_t h0 = pack_hi2(v.x, v.y, &l0);
    uint32_t h1 = pack_hi2(v.z, v.w, &l1);
    uint32_t* ph = (uint32_t*)(g_wqkvh + (size_t)r * QKVN + c);
    uint32_t* pl = (uint32_t*)(g_wqkvl + (size_t)r * QKVN + c);
    ph[0] = h0;
    ph[1] = h1;
    pl[0] = l0;
    pl[1] = l1;
}

// ---------------- plain split: fp32 -> bf16 hi/lo -------------
// sel 1: ext(Wo) -> g_woh/g_wol ; sel 3: ext(Wd) -> g_wdh/g_wdl
__global__ void split_k(const float4* __restrict__ ext, int n4, int sel) {
    int i = blockIdx.x * 256 + threadIdx.x;
    if (i >= n4) return;
    uint32_t* dh;
    uint32_t* dl;
    if (sel == 1) { dh = (uint32_t*)g_woh;  dl = (uint32_t*)g_wol; }
    else          { dh = (uint32_t*)g_wdh;  dl = (uint32_t*)g_wdl; }
    float4 v = ext[i];
    uint32_t l0, l1;
    uint32_t h0 = pack_hi2(v.x, v.y, &l0);
    uint32_t h1 = pack_hi2(v.z, v.w, &l1);
    dh[i*2]   = h0;
    dh[i*2+1] = h1;
    dl[i*2]   = l0;
    dl[i*2+1] = l1;
}

// pack columns: src [rows][cs] -> g_wguh/g_wgul [rows][cd] at column offset off
__global__ void split_pack_k(const float4* __restrict__ s, int n4, int cs, int cd, int off) {
    int i = blockIdx.x * 256 + threadIdx.x;
    if (i >= n4) return;
    float4 v = s[i];
    int el = i * 4;
    int r = el / cs;
    int c = el % cs;
    size_t d = (size_t)r * cd + off + c;
    uint32_t l0, l1;
    uint32_t h0 = pack_hi2(v.x, v.y, &l0);
    uint32_t h1 = pack_hi2(v.z, v.w, &l1);
    uint32_t* ph = (uint32_t*)(g_wguh + d);
    uint32_t* pl = (uint32_t*)(g_wgul + d);
    ph[0] = h0;
    ph[1] = h1;
    pl[0] = l0;
    pl[1] = l1;
}

// ---------------- tensor-core GEMM (bf16x3), 128x128x32 tiles, 3-stage ------
// op 0: QKV   A=g_xnh/l  B=g_wqkvh/l C=g_qkv          dense   N=QKVN K=NHID
// op 1: Oproj A=g_atth/l B=g_woh/l   C=g_h  Cadd=ext  dense   N=NHID K=NHID
// op 2: GU    A=gathered g_xnh/l, B=g_wguh/l C=g_GU   mode1   N=GUN  K=NHID
// op 3: Down  A=g_Gh/l   B=g_wdh/l   C=ext atomic     mode2   N=NHID K=NF
// stage strides: A 20480 B 17408 ; A-lo +10240, B-lo +8704 ; sB = sA + 61440
#define TG_SMEM 113664

__device__ __forceinline__ void tg_load(
        uint32_t sA, uint32_t sB, int stg, int k0,
        int ar, int ac8, int br, int bc8,
        const __nv_bfloat16* aph0, const __nv_bfloat16* apl0, int asz0,
        const __nv_bfloat16* aph1, const __nv_bfloat16* apl1, int asz1,
        const __nv_bfloat16* Bh, const __nv_bfloat16* Bl, int N, int bx) {
    uint32_t a0 = sA + stg * 20480 + ar * 80 + ac8 * 16;
    cpa16(a0,                 aph0 + k0, asz0);
    cpa16(a0 + 10240,         apl0 + k0, asz0);
    cpa16(a0 + 64*80,         aph1 + k0, asz1);
    cpa16(a0 + 10240 + 64*80, apl1 + k0, asz1);
    const __nv_bfloat16* sh0 = Bh + (size_t)(k0 + br) * N + bx + bc8*8;
    const __nv_bfloat16* sl0 = Bl + (size_t)(k0 + br) * N + bx + bc8*8;
    uint32_t b0 = sB + stg * 17408 + br * 272 + bc8 * 16;
    cpa16(b0,                sh0, 16);
    cpa16(b0 + 8704,         sl0, 16);
    cpa16(b0 + 16*272,        sh0 + (size_t)16*N, 16);
    cpa16(b0 + 8704 + 16*272, sl0 + (size_t)16*N, 16);
    asm volatile("cp.async.commit_group;\n");
}

__global__ __launch_bounds__(256) void tgemm_k(int op, const float* __restrict__ cadd_ext,
                                               float* __restrict__ cout_ext) {
    extern __shared__ char smraw[];
    uint32_t sA = (uint32_t)__cvta_generic_to_shared(smraw);
    uint32_t sB = sA + 61440;

    const __nv_bfloat16* Ah;
    const __nv_bfloat16* Al;
    const __nv_bfloat16* Bh;
    const __nv_bfloat16* Bl;
    float* C;
    const float* Cadd = 0;
    int N, K, mode;
    if (op == 0) {
        Ah = g_xnh;  Al = g_xnl;  Bh = g_wqkvh; Bl = g_wqkvl;
        C = g_qkv;  N = QKVN; K = NHID; mode = 0;
    } else if (op == 1) {
        Ah = g_atth; Al = g_attl; Bh = g_woh;   Bl = g_wol;
        C = g_h;    Cadd = cadd_ext; N = NHID; K = NHID; mode = 0;
    } else if (op == 2) {
        Ah = g_xnh;  Al = g_xnl;  Bh = g_wguh;  Bl = g_wgul;
        C = g_GU;   N = GUN;  K = NHID; mode = 1;
    } else {
        Ah = g_Gh;   Al = g_Gl;   Bh = g_wdh;   Bl = g_wdl;
        C = cout_ext; N = NHID; K = NF; mode = 2;
    }

    int tid = threadIdx.x;
    int bx = blockIdx.x * 128;
    int by = blockIdx.y * 128;
    int e = blockIdx.z;
    int m = NTOK;
    if (mode != 0) {
        m = g_cnt[e];
        if (by >= m) return;
        Bh += (size_t)e * K * N;
        Bl += (size_t)e * K * N;
    }

    int ar = tid >> 2;
    int ac8 = tid & 3;
    const __nv_bfloat16* aph0;
    const __nv_bfloat16* apl0;
    const __nv_bfloat16* aph1;
    const __nv_bfloat16* apl1;
    int asz0, asz1;
    {
        int lr0 = by + ar;
        int lr1 = by + ar + 64;
        size_t g0, g1;
        bool v0 = true, v1 = true;
        if (mode == 0) {
            g0 = (size_t)lr0;
            g1 = (size_t)lr1;
        } else if (mode == 1) {
            v0 = lr0 < m;
            v1 = lr1 < m;
            g0 = v0 ? (size_t)g_tok[e * NTOK + lr0] : 0;
            g1 = v1 ? (size_t)g_tok[e * NTOK + lr1] : 0;
        } else {
            v0 = lr0 < m;
            v1 = lr1 < m;
            g0 = (size_t)e * NTOK + (v0 ? (size_t)lr0 : 0);
            g1 = (size_t)e * NTOK + (v1 ? (size_t)lr1 : 0);
        }
        aph0 = Ah + g0 * K + ac8 * 8;
        apl0 = Al + g0 * K + ac8 * 8;
        aph1 = Ah + g1 * K + ac8 * 8;
        apl1 = Al + g1 * K + ac8 * 8;
        asz0 = v0 ? 16 : 0;
        asz1 = v1 ? 16 : 0;
    }
    int br = tid >> 4;
    int bc8 = tid & 15;

    int wid = tid >> 5;
    int lane = tid & 31;
    int wm = (wid >> 2) * 64;
    int wn = (wid & 3) * 32;

    float acc[4][4][4];
    #pragma unroll
    for (int i = 0; i < 4; i++) {
        #pragma unroll
        for (int j = 0; j < 4; j++) {
            #pragma unroll
            for (int r = 0; r < 4; r++) acc[i][j][r] = 0.f;
        }
    }

    int NC = K / 32;
    tg_load(sA, sB, 0, 0,  ar, ac8, br, bc8, aph0, apl0, asz0, aph1, apl1, asz1, Bh, Bl, N, bx);
    tg_load(sA, sB, 1, 32, ar, ac8, br, bc8, aph0, apl0, asz0, aph1, apl1, asz1, Bh, Bl, N, bx);

    for (int c = 0; c < NC; c++) {
        if (c + 1 < NC) {
            asm volatile("cp.async.wait_group 1;\n");
        } else {
            asm volatile("cp.async.wait_group 0;\n");
        }
        __syncthreads();
        int ld = c + 2;
        if (ld < NC) {
            int ls = ld - (ld / 3) * 3;
            tg_load(sA, sB, ls, ld * 32, ar, ac8, br, bc8,
                    aph0, apl0, asz0, aph1, apl1, asz1, Bh, Bl, N, bx);
        }
        int st = c - (c / 3) * 3;
        uint32_t abase = sA + st * 20480;
        uint32_t bbase = sB + st * 17408;

        #pragma unroll
        for (int kk = 0; kk < 32; kk += 16) {
            uint32_t ah[4][4], al[4][4], bh[2][4], bl[2][4];
            int arow = wm + (lane & 15);
            int acolb = (kk + (lane >> 4) * 8) * 2;
            #pragma unroll
            for (int i = 0; i < 4; i++) {
                uint32_t off = abase + (arow + i*16)*80 + acolb;
                ldsm4(ah[i], off);
                ldsm4(al[i], off + 10240);
            }
            int brow = kk + (lane & 15);
            #pragma unroll
            for (int j = 0; j < 2; j++) {
                uint32_t off = bbase + brow*272 + (wn + j*16 + (lane >> 4)*8)*2;
                ldsm4t(bh[j], off);
                ldsm4t(bl[j], off + 8704);
            }
            #pragma unroll
            for (int i = 0; i < 4; i++) {
                #pragma unroll
                for (int n8 = 0; n8 < 4; n8++) {
                    uint32_t b0h = bh[n8>>1][(n8&1)*2];
                    uint32_t b1h = bh[n8>>1][(n8&1)*2+1];
                    uint32_t b0l = bl[n8>>1][(n8&1)*2];
                    uint32_t b1l = bl[n8>>1][(n8&1)*2+1];
                    mma16816(acc[i][n8], ah[i], b0h, b1h);
                    mma16816(acc[i][n8], al[i], b0h, b1h);
                    mma16816(acc[i][n8], ah[i], b0l, b1l);
                }
            }
        }
    }

    int ln4 = lane >> 2;
    int lc = (lane & 3) * 2;
    #pragma unroll
    for (int i = 0; i < 4; i++) {
        int r0 = wm + i * 16 + ln4;
        #pragma unroll
        for (int n8 = 0; n8 < 4; n8++) {
            int gc = bx + wn + n8 * 8 + lc;
            float* a = acc[i][n8];
            if (mode == 0) {
                size_t o0 = (size_t)(by + r0) * N + gc;
                size_t o1 = o0 + (size_t)8 * N;
                if (Cadd) {
                    C[o0]   = a[0] + Cadd[o0];
                    C[o0+1] = a[1] + Cadd[o0+1];
                    C[o1]   = a[2] + Cadd[o1];
                    C[o1+1] = a[3] + Cadd[o1+1];
                } else {
                    float2 w0; w0.x = a[0]; w0.y = a[1];
                    float2 w1; w1.x = a[2]; w1.y = a[3];
                    *(float2*)(C + o0) = w0;
                    *(float2*)(C + o1) = w1;
                }
            } else if (mode == 1) {
                int s0 = by + r0;
                int s1 = s0 + 8;
                if (s0 < m) {
                    float2 w0; w0.x = a[0]; w0.y = a[1];
                    *(float2*)(C + ((size_t)e*NTOK + s0)*N + gc) = w0;
                }
                if (s1 < m) {
                    float2 w1; w1.x = a[2]; w1.y = a[3];
                    *(float2*)(C + ((size_t)e*NTOK + s1)*N + gc) = w1;
                }
            } else {
                int s0 = by + r0;
                int s1 = s0 + 8;
                if (s0 < m) {
                    int tk = g_tok[e*NTOK + s0];
                    float w = g_wgt[e*NTOK + s0];
                    atomicAdd(&C[(size_t)tk*N + gc],   w * a[0]);
                    atomicAdd(&C[(size_t)tk*N + gc+1], w * a[1]);
                }
                if (s1 < m) {
                    int tk = g_tok[e*NTOK + s1];
                    float w = g_wgt[e*NTOK + s1];
                    atomicAdd(&C[(size_t)tk*N + gc],   w * a[2]);
                    atomicAdd(&C[(size_t)tk*N + gc+1], w * a[3]);
                }
            }
        }
    }
}

// -------- flash attention on packed g_qkv [T][1536]; bf16 hi/lo out --------
__global__ __launch_bounds__(64) void flash_k() {
    int qt = blockIdx.x;
    int h = blockIdx.y;
    int b = blockIdx.z;
    int g = h >> 2;
    int tid = threadIdx.x;
    int qrow = qt * 64 + tid;
    size_t t = (size_t)b * NS + qrow;

    float4 q4[16], o4[16];
    const float4* qp = (const float4*)(g_qkv + t * QKVN + h * DH);
    #pragma unroll
    for (int i = 0; i < 16; i++) {
        float4 v = qp[i];
        q4[i].x = v.x * 0.125f;
        q4[i].y = v.y * 0.125f;
        q4[i].z = v.z * 0.125f;
        q4[i].w = v.w * 0.125f;
        o4[i].x = 0.f; o4[i].y = 0.f; o4[i].z = 0.f; o4[i].w = 0.f;
    }
    float m = -INFINITY, l = 0.f;

    __shared__ float4 Ks[32][16];
    __shared__ float4 Vs[32][16];

    int ktmax = (qt * 64 + 63) >> 5;
    for (int kt = 0; kt <= ktmax; kt++) {
        __syncthreads();
        #pragma unroll
        for (int i = 0; i < 8; i++) {
            int f = tid + i * 64;
            int r = f >> 4;
            int c = f & 15;
            size_t krow = (size_t)b * NS + kt * 32 + r;
            Ks[r][c] = ((const float4*)(g_qkv + krow * QKVN + 1024 + g * DH))[c];
            Vs[r][c] = ((const float4*)(g_qkv + krow * QKVN + 1280 + g * DH))[c];
        }
        __syncthreads();

        float s[32];
        int kbase = kt * 32;
        #pragma unroll
        for (int j = 0; j < 32; j++) {
            float acc = 0.f;
            #pragma unroll
            for (int c = 0; c < 16; c++) {
                float4 kv = Ks[j][c];
                acc += q4[c].x*kv.x + q4[c].y*kv.y + q4[c].z*kv.z + q4[c].w*kv.w;
            }
            s[j] = (kbase + j <= qrow) ? acc : -1e9f;
        }
        float mt = m;
        #pragma unroll
        for (int j = 0; j < 32; j++) mt = fmaxf(mt, s[j]);
        float scalef = __expf(m - mt);
        l *= scalef;
        #pragma unroll
        for (int i = 0; i < 16; i++) {
            o4[i].x *= scalef; o4[i].y *= scalef; o4[i].z *= scalef; o4[i].w *= scalef;
        }
        #pragma unroll
        for (int j = 0; j < 32; j++) {
            float p = __expf(s[j] - mt);
            l += p;
            #pragma unroll
            for (int c = 0; c < 16; c++) {
                float4 vv = Vs[j][c];
                o4[c].x += p*vv.x; o4[c].y += p*vv.y; o4[c].z += p*vv.z; o4[c].w += p*vv.w;
            }
        }
        m = mt;
    }
    float inv = 1.0f / l;
    uint32_t* oh = (uint32_t*)(g_atth + t * NHID + h * DH);
    uint32_t* ol = (uint32_t*)(g_attl + t * NHID + h * DH);
    #pragma unroll
    for (int i = 0; i < 16; i++) {
        float a0 = o4[i].x * inv;
        float a1 = o4[i].y * inv;
        float a2 = o4[i].z * inv;
        float a3 = o4[i].w * inv;
        uint32_t l0, l1;
        uint32_t h0 = pack_hi2(a0, a1, &l0);
        uint32_t h1 = pack_hi2(a2, a3, &l1);
        oh[i*2]   = h0;
        oh[i*2+1] = h1;
        ol[i*2]   = l0;
        ol[i*2+1] = l1;
    }
}

// ---------------- router (reads g_xn) ----------------
__global__ void router_k(const float* __restrict__ Wgate) {
    int t = blockIdx.x;
    float acc[NE];
    #pragma unroll
    for (int e = 0; e < NE; e++) acc[e] = 0.f;
    for (int h = threadIdx.x; h < NHID; h += 128) {
        float xv = g_xn[(size_t)t * NHID + h];
        const float4* wr = (const float4*)(Wgate + (size_t)h * NE);
        float4 w0 = wr[0];
        float4 w1 = wr[1];
        acc[0] += xv*w0.x; acc[1] += xv*w0.y; acc[2] += xv*w0.z; acc[3] += xv*w0.w;
        acc[4] += xv*w1.x; acc[5] += xv*w1.y; acc[6] += xv*w1.z; acc[7] += xv*w1.w;
    }
    #pragma unroll
    for (int e = 0; e < NE; e++) {
        #pragma unroll
        for (int o = 16; o; o >>= 1) acc[e] += __shfl_down_sync(0xffffffffu, acc[e], o);
    }
    __shared__ float sm[4][NE];
    int warp = threadIdx.x >> 5;
    int lane = threadIdx.x & 31;
    if (lane == 0) {
        for (int e = 0; e < NE; e++) sm[warp][e] = acc[e];
    }
    __syncthreads();
    if (threadIdx.x == 0) {
        float lg[NE];
        float mx = -INFINITY;
        for (int e = 0; e < NE; e++) {
            lg[e] = sm[0][e] + sm[1][e] + sm[2][e] + sm[3][e];
            mx = fmaxf(mx, lg[e]);
        }
        float p[NE];
        float sum = 0.f;
        for (int e = 0; e < NE; e++) { p[e] = expf(lg[e] - mx); sum += p[e]; }
        float inv = 1.0f / sum;
        for (int e = 0; e < NE; e++) p[e] *= inv;
        int i1 = 0;
        float b1 = p[0];
        for (int e = 1; e < NE; e++) {
            if (p[e] > b1) { b1 = p[e]; i1 = e; }
        }
        int i2 = -1;
        float b2 = -INFINITY;
        for (int e = 0; e < NE; e++) {
            if (e != i1 && p[e] > b2) { b2 = p[e]; i2 = e; }
        }
        int s1 = atomicAdd(&g_cnt[i1], 1);
        g_tok[i1 * NTOK + s1] = t;
        g_wgt[i1 * NTOK + s1] = b1;
        int s2 = atomicAdd(&g_cnt[i2], 1);
        g_tok[i2 * NTOK + s2] = t;
        g_wgt[i2 * NTOK + s2] = b2;
    }
}

__global__ void zero_cnt_k() {
    if (threadIdx.x < NE) g_cnt[threadIdx.x] = 0;
}

// silu(gate)*up from packed g_GU[slot][4096] -> split bf16 g_Gh/g_Gl [slot][2048]
__global__ void silu_k() {
    int slot = blockIdx.x;
    int e = blockIdx.y;
    if (slot >= g_cnt[e]) return;
    size_t b  = ((size_t)e * NTOK + slot) * GUN;
    size_t ob = ((size_t)e * NTOK + slot) * NF;
    for (int f = threadIdx.x * 4; f < NF; f += 1024) {
        float4 g4 = *(const float4*)(g_GU + b + f);
        float4 u4 = *(const float4*)(g_GU + b + NF + f);
        float a0 = g4.x / (1.f + __expf(-g4.x)) * u4.x;
        float a1 = g4.y / (1.f + __expf(-g4.y)) * u4.y;
        float a2 = g4.z / (1.f + __expf(-g4.z)) * u4.z;
        float a3 = g4.w / (1.f + __expf(-g4.w)) * u4.w;
        uint32_t l0, l1;
        uint32_t h0 = pack_hi2(a0, a1, &l0);
        uint32_t h1 = pack_hi2(a2, a3, &l1);
        uint32_t* ph = (uint32_t*)(g_Gh + ob + f);
        uint32_t* pl = (uint32_t*)(g_Gl + ob + f);
        ph[0] = h0;
        ph[1] = h1;
        pl[0] = l0;
        pl[1] = l1;
    }
}

// out = g_h (residual base for down-proj scatter)
__global__ void copy_k(float* __restrict__ dst) {
    size_t i = (size_t)blockIdx.x * 256 + threadIdx.x;
    ((float4*)dst)[i] = ((const float4*)g_h)[i];
}

// ---------------- launch ----------------
extern "C" void kernel_launch(void* const* d_in, const int* in_sizes, int n_in,
                              void* d_out, int out_size) {
    (void)in_sizes; (void)n_in; (void)out_size;
    const float* x     = (const float*)d_in[0];
    const float* w_ln1 = (const float*)d_in[2];
    const float* w_ln2 = (const float*)d_in[3];
    const float* Wq    = (const float*)d_in[4];
    const float* Wk    = (const float*)d_in[5];
    const float* Wv    = (const float*)d_in[6];
    const float* Wo    = (const float*)d_in[7];
    const float* Wgate = (const float*)d_in[8];
    const float* Wg    = (const float*)d_in[9];
    const float* Wu    = (const float*)d_in[10];
    const float* Wd    = (const float*)d_in[11];
    float* out = (float*)d_out;

    cudaFuncSetAttribute(tgemm_k, cudaFuncAttributeMaxDynamicSharedMemorySize, TG_SMEM);

    // 0) ln1 (fused split, no fp32 materialization)
    rmsnorm_split_k<<<NTOK, 256>>>(x, w_ln1, 0, 0);
    // 1) fused QKV weight split-pack
    split_pack_qkv_k<<<NHID*QKVN/4/256, 256>>>((const float4*)Wq, (const float4*)Wk, (const float4*)Wv);
    // 2) Wo split
    split_k<<<NHID*NHID/4/256, 256>>>((const float4*)Wo, NHID*NHID/4, 1);
    // 3) fused QKV projection  <-- target profiled slot
    tgemm_k<<<dim3(QKVN/128, NTOK/128), 256, TG_SMEM>>>(0, 0, 0);
    // 4) attention (writes bf16 hi/lo directly)
    flash_k<<<dim3(NS/64, NHEADS, NB), 64>>>();
    // 5) output proj + residual
    tgemm_k<<<dim3(NHID/128, NTOK/128), 256, TG_SMEM>>>(1, x, 0);
    // 6) ln2 (fused split + fp32 for router)
    rmsnorm_split_k<<<NTOK, 256>>>(0, w_ln2, 1, 1);
    // 7) routing
    zero_cnt_k<<<1, 32>>>();
    router_k<<<NTOK, 128>>>(Wgate);
    // 8) MoE weight splits
    split_pack_k<<<NE*NHID*NF/4/256, 256>>>((const float4*)Wg, NE*NHID*NF/4, NF, GUN, 0);
    split_pack_k<<<NE*NHID*NF/4/256, 256>>>((const float4*)Wu, NE*NHID*NF/4, NF, GUN, NF);
    // 9) fused gate|up grouped GEMM
    tgemm_k<<<dim3(GUN/128, NTOK/128, NE), 256, TG_SMEM>>>(2, 0, 0);
    // 10) silu * up -> split
    silu_k<<<dim3(NTOK, NE), 256>>>();
    // 11) Wd split
    split_k<<<NE*NF*NHID/4/256, 256>>>((const float4*)Wd, NE*NF*NHID/4, 3);
    // 12) residual copy + down-proj scatter
    copy_k<<<NTOK, 256>>>(out);
    tgemm_k<<<dim3(NHID/128, NTOK/128, NE), 256, TG_SMEM>>>(3, 0, out);
}

// round 6
// speedup vs baseline: 1.1134x; 1.1134x over previous
#include <cuda_runtime.h>
#include <cuda_bf16.h>
#include <math.h>
#include <stdint.h>

#define NB    4
#define NS    1024
#define NHID  1024
#define NHEADS 16
#define NKVH  4
#define DH    64
#define NE    8
#define NF    2048
#define NTOK  4096
#define QKVN  1536
#define GUN   4096

// ---------------- scratch (device globals, allocation-free) ----------------
__device__ float g_xn[NTOK * NHID];
__device__ __nv_bfloat16 g_xnh[NTOK * NHID];
__device__ __nv_bfloat16 g_xnl[NTOK * NHID];
__device__ float g_qkv[NTOK * QKVN];
__device__ __nv_bfloat16 g_atth[NTOK * NHID];
__device__ __nv_bfloat16 g_attl[NTOK * NHID];
__device__ float g_h[NTOK * NHID];
__device__ __nv_bfloat16 g_wqkvh[NHID * QKVN];
__device__ __nv_bfloat16 g_wqkvl[NHID * QKVN];
__device__ __nv_bfloat16 g_woh[NHID * NHID];
__device__ __nv_bfloat16 g_wol[NHID * NHID];
__device__ __nv_bfloat16 g_wguh[NE * NHID * GUN];
__device__ __nv_bfloat16 g_wgul[NE * NHID * GUN];
__device__ __nv_bfloat16 g_wdh[NE * NF * NHID];
__device__ __nv_bfloat16 g_wdl[NE * NF * NHID];
__device__ float g_GU[(size_t)NE * NTOK * GUN];
__device__ __nv_bfloat16 g_Gh[NE * NTOK * NF];
__device__ __nv_bfloat16 g_Gl[NE * NTOK * NF];
__device__ int   g_cnt[NE];
__device__ int   g_tok[NE * NTOK];
__device__ float g_wgt[NE * NTOK];

// ---------------- helpers ----------------
__device__ __forceinline__ uint32_t pack_hi2(float a, float b, uint32_t* lo) {
    __nv_bfloat16 ha = __float2bfloat16(a);
    __nv_bfloat16 hb = __float2bfloat16(b);
    __nv_bfloat16 la = __float2bfloat16(a - __bfloat162float(ha));
    __nv_bfloat16 lb = __float2bfloat16(b - __bfloat162float(hb));
    *lo = ((uint32_t)__bfloat16_as_ushort(lb) << 16) | (uint32_t)__bfloat16_as_ushort(la);
    return ((uint32_t)__bfloat16_as_ushort(hb) << 16) | (uint32_t)__bfloat16_as_ushort(ha);
}

__device__ __forceinline__ void ldsm4(uint32_t* r, uint32_t a) {
    asm volatile("ldmatrix.sync.aligned.m8n8.x4.shared.b16 {%0,%1,%2,%3}, [%4];\n"
        : "=r"(r[0]), "=r"(r[1]), "=r"(r[2]), "=r"(r[3]) : "r"(a));
}
__device__ __forceinline__ void ldsm4t(uint32_t* r, uint32_t a) {
    asm volatile("ldmatrix.sync.aligned.m8n8.x4.trans.shared.b16 {%0,%1,%2,%3}, [%4];\n"
        : "=r"(r[0]), "=r"(r[1]), "=r"(r[2]), "=r"(r[3]) : "r"(a));
}
__device__ __forceinline__ void mma16816(float* d, const uint32_t* a, uint32_t b0, uint32_t b1) {
    asm volatile("mma.sync.aligned.m16n8k16.row.col.f32.bf16.bf16.f32 "
        "{%0,%1,%2,%3},{%4,%5,%6,%7},{%8,%9},{%0,%1,%2,%3};\n"
        : "+f"(d[0]), "+f"(d[1]), "+f"(d[2]), "+f"(d[3])
        : "r"(a[0]), "r"(a[1]), "r"(a[2]), "r"(a[3]), "r"(b0), "r"(b1));
}
__device__ __forceinline__ void cpa16(uint32_t dst, const void* src, int sz) {
    asm volatile("cp.async.cg.shared.global [%0], [%1], 16, %2;\n"
        :: "r"(dst), "l"(src), "r"(sz));
}

// ---------------- fused RMSNorm + bf16 hi/lo split ----------------
__global__ void rmsnorm_split_k(const float* __restrict__ xext, const float* __restrict__ w,
                                int use_h, int write_xn) {
    int t = blockIdx.x;
    const float* src = use_h ? (const float*)g_h : xext;
    const float4* xr = (const float4*)(src + (size_t)t * NHID);
    float4 v = xr[threadIdx.x];
    float ss = v.x*v.x + v.y*v.y + v.z*v.z + v.w*v.w;
    #pragma unroll
    for (int o = 16; o; o >>= 1) ss += __shfl_down_sync(0xffffffffu, ss, o);
    __shared__ float red[8];
    if ((threadIdx.x & 31) == 0) red[threadIdx.x >> 5] = ss;
    __syncthreads();
    if (threadIdx.x < 8) {
        float s = red[threadIdx.x];
        #pragma unroll
        for (int o = 4; o; o >>= 1) s += __shfl_down_sync(0xffu, s, o);
        if (threadIdx.x == 0) red[0] = s;
    }
    __syncthreads();
    float rs = rsqrtf(red[0] * (1.0f / NHID) + 1e-6f);
    float4 wv = ((const float4*)w)[threadIdx.x];
    float4 ov;
    ov.x = v.x * rs * wv.x;
    ov.y = v.y * rs * wv.y;
    ov.z = v.z * rs * wv.z;
    ov.w = v.w * rs * wv.w;
    if (write_xn) {
        ((float4*)(g_xn + (size_t)t * NHID))[threadIdx.x] = ov;
    }
    uint32_t l0, l1;
    uint32_t h0 = pack_hi2(ov.x, ov.y, &l0);
    uint32_t h1 = pack_hi2(ov.z, ov.w, &l1);
    uint32_t* ph = (uint32_t*)(g_xnh + (size_t)t * NHID) + threadIdx.x * 2;
    uint32_t* pl = (uint32_t*)(g_xnl + (size_t)t * NHID) + threadIdx.x * 2;
    ph[0] = h0;
    ph[1] = h1;
    pl[0] = l0;
    pl[1] = l1;
}

// ---------------- combined QKV weight split-pack ----------------
__global__ void split_pack_qkv_k(const float4* __restrict__ Wq, const float4* __restrict__ Wk,
                                 const float4* __restrict__ Wv) {
    int i = blockIdx.x * 256 + threadIdx.x;
    int el = i * 4;
    int r = el / QKVN;
    int c = el % QKVN;
    float4 v;
    if (c < 1024)      v = Wq[(r * 1024 + c) / 4];
    else if (c < 1280) v = Wk[(r * 256 + (c - 1024)) / 4];
    else               v = Wv[(r * 256 + (c - 1280)) / 4];
    uint32_t l0, l1;
    uint32_t h0 = pack_hi2(v.x, v.y, &l0);
    uint32_t h1 = pack_hi2(v.z, v.w, &l1);
    uint32_t* ph = (uint32_t*)(g_wqkvh + (size_t)r * QKVN + c);
    uint32_t* pl = (uint32_t*)(g_wqkvl + (size_t)r * QKVN + c);
    ph[0] = h0;
    ph[1] = h1;
    pl[0] = l0;
    pl[1] = l1;
}

// ---------------- plain split: fp32 -> bf16 hi/lo -------------
__global__ void split_k(const float4* __restrict__ ext, int n4, int sel) {
    int i = blockIdx.x * 256 + threadIdx.x;
    if (i >= n4) return;
    uint32_t* dh;
    uint32_t* dl;
    if (sel == 1) { dh = (uint32_t*)g_woh;  dl = (uint32_t*)g_wol; }
    else          { dh = (uint32_t*)g_wdh;  dl = (uint32_t*)g_wdl; }
    float4 v = ext[i];
    uint32_t l0, l1;
    uint32_t h0 = pack_hi2(v.x, v.y, &l0);
    uint32_t h1 = pack_hi2(v.z, v.w, &l1);
    dh[i*2]   = h0;
    dh[i*2+1] = h1;
    dl[i*2]   = l0;
    dl[i*2+1] = l1;
}

// pack columns: src [rows][cs] -> g_wguh/g_wgul [rows][cd] at column offset off
__global__ void split_pack_k(const float4* __restrict__ s, int n4, int cs, int cd, int off) {
    int i = blockIdx.x * 256 + threadIdx.x;
    if (i >= n4) return;
    float4 v = s[i];
    int el = i * 4;
    int r = el / cs;
    int c = el % cs;
    size_t d = (size_t)r * cd + off + c;
    uint32_t l0, l1;
    uint32_t h0 = pack_hi2(v.x, v.y, &l0);
    uint32_t h1 = pack_hi2(v.z, v.w, &l1);
    uint32_t* ph = (uint32_t*)(g_wguh + d);
    uint32_t* pl = (uint32_t*)(g_wgul + d);
    ph[0] = h0;
    ph[1] = h1;
    pl[0] = l0;
    pl[1] = l1;
}

// ---------------- tensor-core GEMM (bf16x3), 128x128x32 tiles, 2-stage ------
// smem: A 2 stages x (2 splits x 128 rows x 80B) = 40960 ; B 2 x (2 x 32 x 272B) = 34816
#define TG_SMEM 75776

__device__ __forceinline__ void tg_load(
        uint32_t sA, uint32_t sB, int stg, int k0,
        int ar, int ac8, int br, int bc8,
        const __nv_bfloat16* aph0, const __nv_bfloat16* apl0, int asz0,
        const __nv_bfloat16* aph1, const __nv_bfloat16* apl1, int asz1,
        const __nv_bfloat16* Bh, const __nv_bfloat16* Bl, int N, int bx) {
    uint32_t a0 = sA + stg * 20480 + ar * 80 + ac8 * 16;
    cpa16(a0,                 aph0 + k0, asz0);
    cpa16(a0 + 10240,         apl0 + k0, asz0);
    cpa16(a0 + 64*80,         aph1 + k0, asz1);
    cpa16(a0 + 10240 + 64*80, apl1 + k0, asz1);
    const __nv_bfloat16* sh0 = Bh + (size_t)(k0 + br) * N + bx + bc8*8;
    const __nv_bfloat16* sl0 = Bl + (size_t)(k0 + br) * N + bx + bc8*8;
    uint32_t b0 = sB + stg * 17408 + br * 272 + bc8 * 16;
    cpa16(b0,                 sh0, 16);
    cpa16(b0 + 8704,          sl0, 16);
    cpa16(b0 + 16*272,        sh0 + (size_t)16*N, 16);
    cpa16(b0 + 8704 + 16*272, sl0 + (size_t)16*N, 16);
    asm volatile("cp.async.commit_group;\n");
}

__global__ __launch_bounds__(256, 2) void tgemm_k(int op, const float* __restrict__ cadd_ext,
                                                  float* __restrict__ cout_ext) {
    extern __shared__ char smraw[];
    uint32_t sA = (uint32_t)__cvta_generic_to_shared(smraw);
    uint32_t sB = sA + 40960;

    const __nv_bfloat16* Ah;
    const __nv_bfloat16* Al;
    const __nv_bfloat16* Bh;
    const __nv_bfloat16* Bl;
    float* C;
    const float* Cadd = 0;
    int N, K, mode;
    if (op == 0) {
        Ah = g_xnh;  Al = g_xnl;  Bh = g_wqkvh; Bl = g_wqkvl;
        C = g_qkv;  N = QKVN; K = NHID; mode = 0;
    } else if (op == 1) {
        Ah = g_atth; Al = g_attl; Bh = g_woh;   Bl = g_wol;
        C = g_h;    Cadd = cadd_ext; N = NHID; K = NHID; mode = 0;
    } else if (op == 2) {
        Ah = g_xnh;  Al = g_xnl;  Bh = g_wguh;  Bl = g_wgul;
        C = g_GU;   N = GUN;  K = NHID; mode = 1;
    } else {
        Ah = g_Gh;   Al = g_Gl;   Bh = g_wdh;   Bl = g_wdl;
        C = cout_ext; N = NHID; K = NF; mode = 2;
    }

    int tid = threadIdx.x;
    int bx = blockIdx.x * 128;
    int by = blockIdx.y * 128;
    int e = blockIdx.z;
    int m = NTOK;
    if (mode != 0) {
        m = g_cnt[e];
        if (by >= m) return;
        Bh += (size_t)e * K * N;
        Bl += (size_t)e * K * N;
    }

    int ar = tid >> 2;
    int ac8 = tid & 3;
    const __nv_bfloat16* aph0;
    const __nv_bfloat16* apl0;
    const __nv_bfloat16* aph1;
    const __nv_bfloat16* apl1;
    int asz0, asz1;
    {
        int lr0 = by + ar;
        int lr1 = by + ar + 64;
        size_t g0, g1;
        bool v0 = true, v1 = true;
        if (mode == 0) {
            g0 = (size_t)lr0;
            g1 = (size_t)lr1;
        } else if (mode == 1) {
            v0 = lr0 < m;
            v1 = lr1 < m;
            g0 = v0 ? (size_t)g_tok[e * NTOK + lr0] : 0;
            g1 = v1 ? (size_t)g_tok[e * NTOK + lr1] : 0;
        } else {
            v0 = lr0 < m;
            v1 = lr1 < m;
            g0 = (size_t)e * NTOK + (v0 ? (size_t)lr0 : 0);
            g1 = (size_t)e * NTOK + (v1 ? (size_t)lr1 : 0);
        }
        aph0 = Ah + g0 * K + ac8 * 8;
        apl0 = Al + g0 * K + ac8 * 8;
        aph1 = Ah + g1 * K + ac8 * 8;
        apl1 = Al + g1 * K + ac8 * 8;
        asz0 = v0 ? 16 : 0;
        asz1 = v1 ? 16 : 0;
    }
    int br = tid >> 4;
    int bc8 = tid & 15;

    int wid = tid >> 5;
    int lane = tid & 31;
    int wm = (wid >> 2) * 64;
    int wn = (wid & 3) * 32;

    float acc[4][4][4];
    #pragma unroll
    for (int i = 0; i < 4; i++) {
        #pragma unroll
        for (int j = 0; j < 4; j++) {
            #pragma unroll
            for (int r = 0; r < 4; r++) acc[i][j][r] = 0.f;
        }
    }

    int NC = K / 32;
    tg_load(sA, sB, 0, 0, ar, ac8, br, bc8, aph0, apl0, asz0, aph1, apl1, asz1, Bh, Bl, N, bx);

    for (int c = 0; c < NC; c++) {
        int buf = c & 1;
        if (c + 1 < NC) {
            tg_load(sA, sB, buf ^ 1, (c + 1) * 32, ar, ac8, br, bc8,
                    aph0, apl0, asz0, aph1, apl1, asz1, Bh, Bl, N, bx);
            asm volatile("cp.async.wait_group 1;\n");
        } else {
            asm volatile("cp.async.wait_group 0;\n");
        }
        __syncthreads();

        uint32_t abase = sA + buf * 20480;
        uint32_t bbase = sB + buf * 17408;

        #pragma unroll
        for (int kk = 0; kk < 32; kk += 16) {
            uint32_t ah[4][4], al[4][4], bh[2][4], bl[2][4];
            int arow = wm + (lane & 15);
            int acolb = (kk + (lane >> 4) * 8) * 2;
            #pragma unroll
            for (int i = 0; i < 4; i++) {
                uint32_t off = abase + (arow + i*16)*80 + acolb;
                ldsm4(ah[i], off);
                ldsm4(al[i], off + 10240);
            }
            int brow = kk + (lane & 15);
            #pragma unroll
            for (int j = 0; j < 2; j++) {
                uint32_t off = bbase + brow*272 + (wn + j*16 + (lane >> 4)*8)*2;
                ldsm4t(bh[j], off);
                ldsm4t(bl[j], off + 8704);
            }
            #pragma unroll
            for (int i = 0; i < 4; i++) {
                #pragma unroll
                for (int n8 = 0; n8 < 4; n8++) {
                    uint32_t b0h = bh[n8>>1][(n8&1)*2];
                    uint32_t b1h = bh[n8>>1][(n8&1)*2+1];
                    uint32_t b0l = bl[n8>>1][(n8&1)*2];
                    uint32_t b1l = bl[n8>>1][(n8&1)*2+1];
                    mma16816(acc[i][n8], ah[i], b0h, b1h);
                    mma16816(acc[i][n8], al[i], b0h, b1h);
                    mma16816(acc[i][n8], ah[i], b0l, b1l);
                }
            }
        }
        __syncthreads();
    }

    int ln4 = lane >> 2;
    int lc = (lane & 3) * 2;
    #pragma unroll
    for (int i = 0; i < 4; i++) {
        int r0 = wm + i * 16 + ln4;
        #pragma unroll
        for (int n8 = 0; n8 < 4; n8++) {
            int gc = bx + wn + n8 * 8 + lc;
            float* a = acc[i][n8];
            if (mode == 0) {
                size_t o0 = (size_t)(by + r0) * N + gc;
                size_t o1 = o0 + (size_t)8 * N;
                if (Cadd) {
                    C[o0]   = a[0] + Cadd[o0];
                    C[o0+1] = a[1] + Cadd[o0+1];
                    C[o1]   = a[2] + Cadd[o1];
                    C[o1+1] = a[3] + Cadd[o1+1];
                } else {
                    float2 w0; w0.x = a[0]; w0.y = a[1];
                    float2 w1; w1.x = a[2]; w1.y = a[3];
                    *(float2*)(C + o0) = w0;
                    *(float2*)(C + o1) = w1;
                }
            } else if (mode == 1) {
                int s0 = by + r0;
                int s1 = s0 + 8;
                if (s0 < m) {
                    float2 w0; w0.x = a[0]; w0.y = a[1];
                    *(float2*)(C + ((size_t)e*NTOK + s0)*N + gc) = w0;
                }
                if (s1 < m) {
                    float2 w1; w1.x = a[2]; w1.y = a[3];
                    *(float2*)(C + ((size_t)e*NTOK + s1)*N + gc) = w1;
                }
            } else {
                int s0 = by + r0;
                int s1 = s0 + 8;
                if (s0 < m) {
                    int tk = g_tok[e*NTOK + s0];
                    float w = g_wgt[e*NTOK + s0];
                    atomicAdd(&C[(size_t)tk*N + gc],   w * a[0]);
                    atomicAdd(&C[(size_t)tk*N + gc+1], w * a[1]);
                }
                if (s1 < m) {
                    int tk = g_tok[e*NTOK + s1];
                    float w = g_wgt[e*NTOK + s1];
                    atomicAdd(&C[(size_t)tk*N + gc],   w * a[2]);
                    atomicAdd(&C[(size_t)tk*N + gc+1], w * a[3]);
                }
            }
        }
    }
}

// -------- flash attention on packed g_qkv [T][1536]; bf16 hi/lo out --------
__global__ __launch_bounds__(64) void flash_k() {
    int qt = blockIdx.x;
    int h = blockIdx.y;
    int b = blockIdx.z;
    int g = h >> 2;
    int tid = threadIdx.x;
    int qrow = qt * 64 + tid;
    size_t t = (size_t)b * NS + qrow;

    float4 q4[16], o4[16];
    const float4* qp = (const float4*)(g_qkv + t * QKVN + h * DH);
    #pragma unroll
    for (int i = 0; i < 16; i++) {
        float4 v = qp[i];
        q4[i].x = v.x * 0.125f;
        q4[i].y = v.y * 0.125f;
        q4[i].z = v.z * 0.125f;
        q4[i].w = v.w * 0.125f;
        o4[i].x = 0.f; o4[i].y = 0.f; o4[i].z = 0.f; o4[i].w = 0.f;
    }
    float m = -INFINITY, l = 0.f;

    __shared__ float4 Ks[32][16];
    __shared__ float4 Vs[32][16];

    int ktmax = (qt * 64 + 63) >> 5;
    for (int kt = 0; kt <= ktmax; kt++) {
        __syncthreads();
        #pragma unroll
        for (int i = 0; i < 8; i++) {
            int f = tid + i * 64;
            int r = f >> 4;
            int c = f & 15;
            size_t krow = (size_t)b * NS + kt * 32 + r;
            Ks[r][c] = ((const float4*)(g_qkv + krow * QKVN + 1024 + g * DH))[c];
            Vs[r][c] = ((const float4*)(g_qkv + krow * QKVN + 1280 + g * DH))[c];
        }
        __syncthreads();

        float s[32];
        int kbase = kt * 32;
        #pragma unroll
        for (int j = 0; j < 32; j++) {
            float acc = 0.f;
            #pragma unroll
            for (int c = 0; c < 16; c++) {
                float4 kv = Ks[j][c];
                acc += q4[c].x*kv.x + q4[c].y*kv.y + q4[c].z*kv.z + q4[c].w*kv.w;
            }
            s[j] = (kbase + j <= qrow) ? acc : -1e9f;
        }
        float mt = m;
        #pragma unroll
        for (int j = 0; j < 32; j++) mt = fmaxf(mt, s[j]);
        float scalef = __expf(m - mt);
        l *= scalef;
        #pragma unroll
        for (int i = 0; i < 16; i++) {
            o4[i].x *= scalef; o4[i].y *= scalef; o4[i].z *= scalef; o4[i].w *= scalef;
        }
        #pragma unroll
        for (int j = 0; j < 32; j++) {
            float p = __expf(s[j] - mt);
            l += p;
            #pragma unroll
            for (int c = 0; c < 16; c++) {
                float4 vv = Vs[j][c];
                o4[c].x += p*vv.x; o4[c].y += p*vv.y; o4[c].z += p*vv.z; o4[c].w += p*vv.w;
            }
        }
        m = mt;
    }
    float inv = 1.0f / l;
    uint32_t* oh = (uint32_t*)(g_atth + t * NHID + h * DH);
    uint32_t* ol = (uint32_t*)(g_attl + t * NHID + h * DH);
    #pragma unroll
    for (int i = 0; i < 16; i++) {
        float a0 = o4[i].x * inv;
        float a1 = o4[i].y * inv;
        float a2 = o4[i].z * inv;
        float a3 = o4[i].w * inv;
        uint32_t l0, l1;
        uint32_t h0 = pack_hi2(a0, a1, &l0);
        uint32_t h1 = pack_hi2(a2, a3, &l1);
        oh[i*2]   = h0;
        oh[i*2+1] = h1;
        ol[i*2]   = l0;
        ol[i*2+1] = l1;
    }
}

// ---------------- router (reads g_xn) ----------------
__global__ void router_k(const float* __restrict__ Wgate) {
    int t = blockIdx.x;
    float acc[NE];
    #pragma unroll
    for (int e = 0; e < NE; e++) acc[e] = 0.f;
    for (int h = threadIdx.x; h < NHID; h += 128) {
        float xv = g_xn[(size_t)t * NHID + h];
        const float4* wr = (const float4*)(Wgate + (size_t)h * NE);
        float4 w0 = wr[0];
        float4 w1 = wr[1];
        acc[0] += xv*w0.x; acc[1] += xv*w0.y; acc[2] += xv*w0.z; acc[3] += xv*w0.w;
        acc[4] += xv*w1.x; acc[5] += xv*w1.y; acc[6] += xv*w1.z; acc[7] += xv*w1.w;
    }
    #pragma unroll
    for (int e = 0; e < NE; e++) {
        #pragma unroll
        for (int o = 16; o; o >>= 1) acc[e] += __shfl_down_sync(0xffffffffu, acc[e], o);
    }
    __shared__ float sm[4][NE];
    int warp = threadIdx.x >> 5;
    int lane = threadIdx.x & 31;
    if (lane == 0) {
        for (int e = 0; e < NE; e++) sm[warp][e] = acc[e];
    }
    __syncthreads();
    if (threadIdx.x == 0) {
        float lg[NE];
        float mx = -INFINITY;
        for (int e = 0; e < NE; e++) {
            lg[e] = sm[0][e] + sm[1][e] + sm[2][e] + sm[3][e];
            mx = fmaxf(mx, lg[e]);
        }
        float p[NE];
        float sum = 0.f;
        for (int e = 0; e < NE; e++) { p[e] = expf(lg[e] - mx); sum += p[e]; }
        float inv = 1.0f / sum;
        for (int e = 0; e < NE; e++) p[e] *= inv;
        int i1 = 0;
        float b1 = p[0];
        for (int e = 1; e < NE; e++) {
            if (p[e] > b1) { b1 = p[e]; i1 = e; }
        }
        int i2 = -1;
        float b2 = -INFINITY;
        for (int e = 0; e < NE; e++) {
            if (e != i1 && p[e] > b2) { b2 = p[e]; i2 = e; }
        }
        int s1 = atomicAdd(&g_cnt[i1], 1);
        g_tok[i1 * NTOK + s1] = t;
        g_wgt[i1 * NTOK + s1] = b1;
        int s2 = atomicAdd(&g_cnt[i2], 1);
        g_tok[i2 * NTOK + s2] = t;
        g_wgt[i2 * NTOK + s2] = b2;
    }
}

__global__ void zero_cnt_k() {
    if (threadIdx.x < NE) g_cnt[threadIdx.x] = 0;
}

// silu(gate)*up from packed g_GU[slot][4096] -> split bf16 g_Gh/g_Gl [slot][2048]
__global__ void silu_k() {
    int slot = blockIdx.x;
    int e = blockIdx.y;
    if (slot >= g_cnt[e]) return;
    size_t b  = ((size_t)e * NTOK + slot) * GUN;
    size_t ob = ((size_t)e * NTOK + slot) * NF;
    for (int f = threadIdx.x * 4; f < NF; f += 1024) {
        float4 g4 = *(const float4*)(g_GU + b + f);
        float4 u4 = *(const float4*)(g_GU + b + NF + f);
        float a0 = g4.x / (1.f + __expf(-g4.x)) * u4.x;
        float a1 = g4.y / (1.f + __expf(-g4.y)) * u4.y;
        float a2 = g4.z / (1.f + __expf(-g4.z)) * u4.z;
        float a3 = g4.w / (1.f + __expf(-g4.w)) * u4.w;
        uint32_t l0, l1;
        uint32_t h0 = pack_hi2(a0, a1, &l0);
        uint32_t h1 = pack_hi2(a2, a3, &l1);
        uint32_t* ph = (uint32_t*)(g_Gh + ob + f);
        uint32_t* pl = (uint32_t*)(g_Gl + ob + f);
        ph[0] = h0;
        ph[1] = h1;
        pl[0] = l0;
        pl[1] = l1;
    }
}

// out = g_h (residual base for down-proj scatter)
__global__ void copy_k(float* __restrict__ dst) {
    size_t i = (size_t)blockIdx.x * 256 + threadIdx.x;
    ((float4*)dst)[i] = ((const float4*)g_h)[i];
}

// ---------------- launch ----------------
extern "C" void kernel_launch(void* const* d_in, const int* in_sizes, int n_in,
                              void* d_out, int out_size) {
    (void)in_sizes; (void)n_in; (void)out_size;
    const float* x     = (const float*)d_in[0];
    const float* w_ln1 = (const float*)d_in[2];
    const float* w_ln2 = (const float*)d_in[3];
    const float* Wq    = (const float*)d_in[4];
    const float* Wk    = (const float*)d_in[5];
    const float* Wv    = (const float*)d_in[6];
    const float* Wo    = (const float*)d_in[7];
    const float* Wgate = (const float*)d_in[8];
    const float* Wg    = (const float*)d_in[9];
    const float* Wu    = (const float*)d_in[10];
    const float* Wd    = (const float*)d_in[11];
    float* out = (float*)d_out;

    cudaFuncSetAttribute(tgemm_k, cudaFuncAttributeMaxDynamicSharedMemorySize, TG_SMEM);

    // 0) ln1 (fused split)
    rmsnorm_split_k<<<NTOK, 256>>>(x, w_ln1, 0, 0);
    // 1) fused QKV weight split-pack
    split_pack_qkv_k<<<NHID*QKVN/4/256, 256>>>((const float4*)Wq, (const float4*)Wk, (const float4*)Wv);
    // 2) Wo split
    split_k<<<NHID*NHID/4/256, 256>>>((const float4*)Wo, NHID*NHID/4, 1);
    // 3) fused QKV projection  <-- profiled slot
    tgemm_k<<<dim3(QKVN/128, NTOK/128), 256, TG_SMEM>>>(0, 0, 0);
    // 4) attention (writes bf16 hi/lo directly)
    flash_k<<<dim3(NS/64, NHEADS, NB), 64>>>();
    // 5) output proj + residual
    tgemm_k<<<dim3(NHID/128, NTOK/128), 256, TG_SMEM>>>(1, x, 0);
    // 6) ln2 (fused split + fp32 for router)
    rmsnorm_split_k<<<NTOK, 256>>>(0, w_ln2, 1, 1);
    // 7) routing
    zero_cnt_k<<<1, 32>>>();
    router_k<<<NTOK, 128>>>(Wgate);
    // 8) MoE weight splits
    split_pack_k<<<NE*NHID*NF/4/256, 256>>>((const float4*)Wg, NE*NHID*NF/4, NF, GUN, 0);
    split_pack_k<<<NE*NHID*NF/4/256, 256>>>((const float4*)Wu, NE*NHID*NF/4, NF, GUN, NF);
    // 9) fused gate|up grouped GEMM
    tgemm_k<<<dim3(GUN/128, NTOK/128, NE), 256, TG_SMEM>>>(2, 0, 0);
    // 10) silu * up -> split
    silu_k<<<dim3(NTOK, NE), 256>>>();
    // 11) Wd split
    split_k<<<NE*NF*NHID/4/256, 256>>>((const float4*)Wd, NE*NF*NHID/4, 3);
    // 12) residual copy + down-proj scatter
    copy_k<<<NTOK, 256>>>(out);
    tgemm_k<<<dim3(NHID/128, NTOK/128, NE), 256, TG_SMEM>>>(3, 0, out);
}

// round 8
// speedup vs baseline: 1.2902x; 1.1588x over previous
#include <cuda_runtime.h>
#include <cuda_bf16.h>
#include <math.h>
#include <stdint.h>

#define NB    4
#define NS    1024
#define NHID  1024
#define NHEADS 16
#define NKVH  4
#define DH    64
#define NE    8
#define NF    2048
#define NTOK  4096
#define QKVN  1536
#define GUN   4096

// ---------------- scratch (device globals, allocation-free) ----------------
__device__ float g_xn[NTOK * NHID];
__device__ __nv_bfloat16 g_xnh[NTOK * NHID];
__device__ __nv_bfloat16 g_xnl[NTOK * NHID];
__device__ float g_qkv[NTOK * QKVN];
__device__ __nv_bfloat16 g_atth[NTOK * NHID];
__device__ __nv_bfloat16 g_attl[NTOK * NHID];
__device__ float g_h[NTOK * NHID];
__device__ __nv_bfloat16 g_wqkvh[NHID * QKVN];
__device__ __nv_bfloat16 g_wqkvl[NHID * QKVN];
__device__ __nv_bfloat16 g_woh[NHID * NHID];
__device__ __nv_bfloat16 g_wol[NHID * NHID];
__device__ __nv_bfloat16 g_wguh[NE * NHID * GUN];
__device__ __nv_bfloat16 g_wgul[NE * NHID * GUN];
__device__ __nv_bfloat16 g_wdh[NE * NF * NHID];
__device__ __nv_bfloat16 g_wdl[NE * NF * NHID];
__device__ float g_GU[(size_t)NE * NTOK * GUN];
__device__ __nv_bfloat16 g_Gh[NE * NTOK * NF];
__device__ __nv_bfloat16 g_Gl[NE * NTOK * NF];
__device__ int   g_cnt[NE];
__device__ int   g_tok[NE * NTOK];
__device__ float g_wgt[NE * NTOK];

// ---------------- helpers ----------------
__device__ __forceinline__ uint32_t pack_hi2(float a, float b, uint32_t* lo) {
    __nv_bfloat16 ha = __float2bfloat16(a);
    __nv_bfloat16 hb = __float2bfloat16(b);
    __nv_bfloat16 la = __float2bfloat16(a - __bfloat162float(ha));
    __nv_bfloat16 lb = __float2bfloat16(b - __bfloat162float(hb));
    *lo = ((uint32_t)__bfloat16_as_ushort(lb) << 16) | (uint32_t)__bfloat16_as_ushort(la);
    return ((uint32_t)__bfloat16_as_ushort(hb) << 16) | (uint32_t)__bfloat16_as_ushort(ha);
}

__device__ __forceinline__ void ldsm4(uint32_t* r, uint32_t a) {
    asm volatile("ldmatrix.sync.aligned.m8n8.x4.shared.b16 {%0,%1,%2,%3}, [%4];\n"
        : "=r"(r[0]), "=r"(r[1]), "=r"(r[2]), "=r"(r[3]) : "r"(a));
}
__device__ __forceinline__ void ldsm4t(uint32_t* r, uint32_t a) {
    asm volatile("ldmatrix.sync.aligned.m8n8.x4.trans.shared.b16 {%0,%1,%2,%3}, [%4];\n"
        : "=r"(r[0]), "=r"(r[1]), "=r"(r[2]), "=r"(r[3]) : "r"(a));
}
__device__ __forceinline__ void mma16816(float* d, const uint32_t* a, uint32_t b0, uint32_t b1) {
    asm volatile("mma.sync.aligned.m16n8k16.row.col.f32.bf16.bf16.f32 "
        "{%0,%1,%2,%3},{%4,%5,%6,%7},{%8,%9},{%0,%1,%2,%3};\n"
        : "+f"(d[0]), "+f"(d[1]), "+f"(d[2]), "+f"(d[3])
        : "r"(a[0]), "r"(a[1]), "r"(a[2]), "r"(a[3]), "r"(b0), "r"(b1));
}
__device__ __forceinline__ void cpa16(uint32_t dst, const void* src, int sz) {
    asm volatile("cp.async.cg.shared.global [%0], [%1], 16, %2;\n"
        :: "r"(dst), "l"(src), "r"(sz));
}

// ---- packed f32x2 (sm_100+ family, not 'a'-gated) ----
struct __align__(16) ull2_t { unsigned long long x, y; };
__device__ __forceinline__ unsigned long long pk2(float a, float b) {
    unsigned long long r;
    asm("mov.b64 %0, {%1, %2};" : "=l"(r) : "f"(a), "f"(b));
    return r;
}
__device__ __forceinline__ void upk2(unsigned long long v, float* a, float* b) {
    asm("mov.b64 {%0, %1}, %2;" : "=f"(*a), "=f"(*b) : "l"(v));
}
__device__ __forceinline__ unsigned long long fma2(unsigned long long a, unsigned long long b,
                                                   unsigned long long c) {
    unsigned long long d;
    asm("fma.rn.f32x2 %0, %1, %2, %3;" : "=l"(d) : "l"(a), "l"(b), "l"(c));
    return d;
}
__device__ __forceinline__ unsigned long long mul2(unsigned long long a, unsigned long long b) {
    unsigned long long d;
    asm("mul.rn.f32x2 %0, %1, %2;" : "=l"(d) : "l"(a), "l"(b));
    return d;
}

// ---------------- fused RMSNorm + bf16 hi/lo split ----------------
__global__ void rmsnorm_split_k(const float* __restrict__ xext, const float* __restrict__ w,
                                int use_h, int write_xn) {
    int t = blockIdx.x;
    const float* src = use_h ? (const float*)g_h : xext;
    const float4* xr = (const float4*)(src + (size_t)t * NHID);
    float4 v = xr[threadIdx.x];
    float ss = v.x*v.x + v.y*v.y + v.z*v.z + v.w*v.w;
    #pragma unroll
    for (int o = 16; o; o >>= 1) ss += __shfl_down_sync(0xffffffffu, ss, o);
    __shared__ float red[8];
    if ((threadIdx.x & 31) == 0) red[threadIdx.x >> 5] = ss;
    __syncthreads();
    if (threadIdx.x < 8) {
        float s = red[threadIdx.x];
        #pragma unroll
        for (int o = 4; o; o >>= 1) s += __shfl_down_sync(0xffu, s, o);
        if (threadIdx.x == 0) red[0] = s;
    }
    __syncthreads();
    float rs = rsqrtf(red[0] * (1.0f / NHID) + 1e-6f);
    float4 wv = ((const float4*)w)[threadIdx.x];
    float4 ov;
    ov.x = v.x * rs * wv.x;
    ov.y = v.y * rs * wv.y;
    ov.z = v.z * rs * wv.z;
    ov.w = v.w * rs * wv.w;
    if (write_xn) {
        ((float4*)(g_xn + (size_t)t * NHID))[threadIdx.x] = ov;
    }
    uint32_t l0, l1;
    uint32_t h0 = pack_hi2(ov.x, ov.y, &l0);
    uint32_t h1 = pack_hi2(ov.z, ov.w, &l1);
    uint32_t* ph = (uint32_t*)(g_xnh + (size_t)t * NHID) + threadIdx.x * 2;
    uint32_t* pl = (uint32_t*)(g_xnl + (size_t)t * NHID) + threadIdx.x * 2;
    ph[0] = h0;
    ph[1] = h1;
    pl[0] = l0;
    pl[1] = l1;
}

// ---------------- combined QKV weight split-pack ----------------
__global__ void split_pack_qkv_k(const float4* __restrict__ Wq, const float4* __restrict__ Wk,
                                 const float4* __restrict__ Wv) {
    int i = blockIdx.x * 256 + threadIdx.x;
    int el = i * 4;
    int r = el / QKVN;
    int c = el % QKVN;
    float4 v;
    if (c < 1024)      v = Wq[(r * 1024 + c) / 4];
    else if (c < 1280) v = Wk[(r * 256 + (c - 1024)) / 4];
    else               v = Wv[(r * 256 + (c - 1280)) / 4];
    uint32_t l0, l1;
    uint32_t h0 = pack_hi2(v.x, v.y, &l0);
    uint32_t h1 = pack_hi2(v.z, v.w, &l1);
    uint32_t* ph = (uint32_t*)(g_wqkvh + (size_t)r * QKVN + c);
    uint32_t* pl = (uint32_t*)(g_wqkvl + (size_t)r * QKVN + c);
    ph[0] = h0;
    ph[1] = h1;
    pl[0] = l0;
    pl[1] = l1;
}

// ---------------- plain split: fp32 -> bf16 hi/lo -------------
__global__ void split_k(const float4* __restrict__ ext, int n4, int sel) {
    int i = blockIdx.x * 256 + threadIdx.x;
    if (i >= n4) return;
    uint32_t* dh;
    uint32_t* dl;
    if (sel == 1) { dh = (uint32_t*)g_woh;  dl = (uint32_t*)g_wol; }
    else          { dh = (uint32_t*)g_wdh;  dl = (uint32_t*)g_wdl; }
    float4 v = ext[i];
    uint32_t l0, l1;
    uint32_t h0 = pack_hi2(v.x, v.y, &l0);
    uint32_t h1 = pack_hi2(v.z, v.w, &l1);
    dh[i*2]   = h0;
    dh[i*2+1] = h1;
    dl[i*2]   = l0;
    dl[i*2+1] = l1;
}

// pack columns: src [rows][cs] -> g_wguh/g_wgul [rows][cd] at column offset off
__global__ void split_pack_k(const float4* __restrict__ s, int n4, int cs, int cd, int off) {
    int i = blockIdx.x * 256 + threadIdx.x;
    if (i >= n4) return;
    float4 v = s[i];
    int el = i * 4;
    int r = el / cs;
    int c = el % cs;
    size_t d = (size_t)r * cd + off + c;
    uint32_t l0, l1;
    uint32_t h0 = pack_hi2(v.x, v.y, &l0);
    uint32_t h1 = pack_hi2(v.z, v.w, &l1);
    uint32_t* ph = (uint32_t*)(g_wguh + d);
    uint32_t* pl = (uint32_t*)(g_wgul + d);
    ph[0] = h0;
    ph[1] = h1;
    pl[0] = l0;
    pl[1] = l1;
}

// ---------------- tensor-core GEMM (bf16x3), 128x128x32 tiles, 2-stage ------
#define TG_SMEM 75776

__device__ __forceinline__ void tg_load(
        uint32_t sA, uint32_t sB, int stg, int k0,
        int ar, int ac8, int br, int bc8,
        const __nv_bfloat16* aph0, const __nv_bfloat16* apl0, int asz0,
        const __nv_bfloat16* aph1, const __nv_bfloat16* apl1, int asz1,
        const __nv_bfloat16* Bh, const __nv_bfloat16* Bl, int N, int bx) {
    uint32_t a0 = sA + stg * 20480 + ar * 80 + ac8 * 16;
    cpa16(a0,                 aph0 + k0, asz0);
    cpa16(a0 + 10240,         apl0 + k0, asz0);
    cpa16(a0 + 64*80,         aph1 + k0, asz1);
    cpa16(a0 + 10240 + 64*80, apl1 + k0, asz1);
    const __nv_bfloat16* sh0 = Bh + (size_t)(k0 + br) * N + bx + bc8*8;
    const __nv_bfloat16* sl0 = Bl + (size_t)(k0 + br) * N + bx + bc8*8;
    uint32_t b0 = sB + stg * 17408 + br * 272 + bc8 * 16;
    cpa16(b0,                 sh0, 16);
    cpa16(b0 + 8704,          sl0, 16);
    cpa16(b0 + 16*272,        sh0 + (size_t)16*N, 16);
    cpa16(b0 + 8704 + 16*272, sl0 + (size_t)16*N, 16);
    asm volatile("cp.async.commit_group;\n");
}

__global__ __launch_bounds__(256, 2) void tgemm_k(int op, const float* __restrict__ cadd_ext,
                                                  float* __restrict__ cout_ext) {
    extern __shared__ char smraw[];
    uint32_t sA = (uint32_t)__cvta_generic_to_shared(smraw);
    uint32_t sB = sA + 40960;

    const __nv_bfloat16* Ah;
    const __nv_bfloat16* Al;
    const __nv_bfloat16* Bh;
    const __nv_bfloat16* Bl;
    float* C;
    const float* Cadd = 0;
    int N, K, mode;
    if (op == 0) {
        Ah = g_xnh;  Al = g_xnl;  Bh = g_wqkvh; Bl = g_wqkvl;
        C = g_qkv;  N = QKVN; K = NHID; mode = 0;
    } else if (op == 1) {
        Ah = g_atth; Al = g_attl; Bh = g_woh;   Bl = g_wol;
        C = g_h;    Cadd = cadd_ext; N = NHID; K = NHID; mode = 0;
    } else if (op == 2) {
        Ah = g_xnh;  Al = g_xnl;  Bh = g_wguh;  Bl = g_wgul;
        C = g_GU;   N = GUN;  K = NHID; mode = 1;
    } else {
        Ah = g_Gh;   Al = g_Gl;   Bh = g_wdh;   Bl = g_wdl;
        C = cout_ext; N = NHID; K = NF; mode = 2;
    }

    int tid = threadIdx.x;
    int bx = blockIdx.x * 128;
    int by = blockIdx.y * 128;
    int e = blockIdx.z;
    int m = NTOK;
    if (mode != 0) {
        m = g_cnt[e];
        if (by >= m) return;
        Bh += (size_t)e * K * N;
        Bl += (size_t)e * K * N;
    }

    int ar = tid >> 2;
    int ac8 = tid & 3;
    const __nv_bfloat16* aph0;
    const __nv_bfloat16* apl0;
    const __nv_bfloat16* aph1;
    const __nv_bfloat16* apl1;
    int asz0, asz1;
    {
        int lr0 = by + ar;
        int lr1 = by + ar + 64;
        size_t g0, g1;
        bool v0 = true, v1 = true;
        if (mode == 0) {
            g0 = (size_t)lr0;
            g1 = (size_t)lr1;
        } else if (mode == 1) {
            v0 = lr0 < m;
            v1 = lr1 < m;
            g0 = v0 ? (size_t)g_tok[e * NTOK + lr0] : 0;
            g1 = v1 ? (size_t)g_tok[e * NTOK + lr1] : 0;
        } else {
            v0 = lr0 < m;
            v1 = lr1 < m;
            g0 = (size_t)e * NTOK + (v0 ? (size_t)lr0 : 0);
            g1 = (size_t)e * NTOK + (v1 ? (size_t)lr1 : 0);
        }
        aph0 = Ah + g0 * K + ac8 * 8;
        apl0 = Al + g0 * K + ac8 * 8;
        aph1 = Ah + g1 * K + ac8 * 8;
        apl1 = Al + g1 * K + ac8 * 8;
        asz0 = v0 ? 16 : 0;
        asz1 = v1 ? 16 : 0;
    }
    int br = tid >> 4;
    int bc8 = tid & 15;

    int wid = tid >> 5;
    int lane = tid & 31;
    int wm = (wid >> 2) * 64;
    int wn = (wid & 3) * 32;

    float acc[4][4][4];
    #pragma unroll
    for (int i = 0; i < 4; i++) {
        #pragma unroll
        for (int j = 0; j < 4; j++) {
            #pragma unroll
            for (int r = 0; r < 4; r++) acc[i][j][r] = 0.f;
        }
    }

    int NC = K / 32;
    tg_load(sA, sB, 0, 0, ar, ac8, br, bc8, aph0, apl0, asz0, aph1, apl1, asz1, Bh, Bl, N, bx);

    for (int c = 0; c < NC; c++) {
        int buf = c & 1;
        if (c + 1 < NC) {
            tg_load(sA, sB, buf ^ 1, (c + 1) * 32, ar, ac8, br, bc8,
                    aph0, apl0, asz0, aph1, apl1, asz1, Bh, Bl, N, bx);
            asm volatile("cp.async.wait_group 1;\n");
        } else {
            asm volatile("cp.async.wait_group 0;\n");
        }
        __syncthreads();

        uint32_t abase = sA + buf * 20480;
        uint32_t bbase = sB + buf * 17408;

        #pragma unroll
        for (int kk = 0; kk < 32; kk += 16) {
            uint32_t ah[4][4], al[4][4], bh[2][4], bl[2][4];
            int arow = wm + (lane & 15);
            int acolb = (kk + (lane >> 4) * 8) * 2;
            #pragma unroll
            for (int i = 0; i < 4; i++) {
                uint32_t off = abase + (arow + i*16)*80 + acolb;
                ldsm4(ah[i], off);
                ldsm4(al[i], off + 10240);
            }
            int brow = kk + (lane & 15);
            #pragma unroll
            for (int j = 0; j < 2; j++) {
                uint32_t off = bbase + brow*272 + (wn + j*16 + (lane >> 4)*8)*2;
                ldsm4t(bh[j], off);
                ldsm4t(bl[j], off + 8704);
            }
            #pragma unroll
            for (int i = 0; i < 4; i++) {
                #pragma unroll
                for (int n8 = 0; n8 < 4; n8++) {
                    uint32_t b0h = bh[n8>>1][(n8&1)*2];
                    uint32_t b1h = bh[n8>>1][(n8&1)*2+1];
                    uint32_t b0l = bl[n8>>1][(n8&1)*2];
                    uint32_t b1l = bl[n8>>1][(n8&1)*2+1];
                    mma16816(acc[i][n8], ah[i], b0h, b1h);
                    mma16816(acc[i][n8], al[i], b0h, b1h);
                    mma16816(acc[i][n8], ah[i], b0l, b1l);
                }
            }
        }
        __syncthreads();
    }

    int ln4 = lane >> 2;
    int lc = (lane & 3) * 2;
    #pragma unroll
    for (int i = 0; i < 4; i++) {
        int r0 = wm + i * 16 + ln4;
        #pragma unroll
        for (int n8 = 0; n8 < 4; n8++) {
            int gc = bx + wn + n8 * 8 + lc;
            float* a = acc[i][n8];
            if (mode == 0) {
                size_t o0 = (size_t)(by + r0) * N + gc;
                size_t o1 = o0 + (size_t)8 * N;
                if (Cadd) {
                    C[o0]   = a[0] + Cadd[o0];
                    C[o0+1] = a[1] + Cadd[o0+1];
                    C[o1]   = a[2] + Cadd[o1];
                    C[o1+1] = a[3] + Cadd[o1+1];
                } else {
                    float2 w0; w0.x = a[0]; w0.y = a[1];
                    float2 w1; w1.x = a[2]; w1.y = a[3];
                    *(float2*)(C + o0) = w0;
                    *(float2*)(C + o1) = w1;
                }
            } else if (mode == 1) {
                int s0 = by + r0;
                int s1 = s0 + 8;
                if (s0 < m) {
                    float2 w0; w0.x = a[0]; w0.y = a[1];
                    *(float2*)(C + ((size_t)e*NTOK + s0)*N + gc) = w0;
                }
                if (s1 < m) {
                    float2 w1; w1.x = a[2]; w1.y = a[3];
                    *(float2*)(C + ((size_t)e*NTOK + s1)*N + gc) = w1;
                }
            } else {
                int s0 = by + r0;
                int s1 = s0 + 8;
                if (s0 < m) {
                    int tk = g_tok[e*NTOK + s0];
                    float w = g_wgt[e*NTOK + s0];
                    atomicAdd(&C[(size_t)tk*N + gc],   w * a[0]);
                    atomicAdd(&C[(size_t)tk*N + gc+1], w * a[1]);
                }
                if (s1 < m) {
                    int tk = g_tok[e*NTOK + s1];
                    float w = g_wgt[e*NTOK + s1];
                    atomicAdd(&C[(size_t)tk*N + gc],   w * a[2]);
                    atomicAdd(&C[(size_t)tk*N + gc+1], w * a[3]);
                }
            }
        }
    }
}

// -------- flash attention, 128-row q tiles, packed f32x2 FMA ---------------
__global__ __launch_bounds__(128) void flash_k() {
    int qt = blockIdx.x;
    int h = blockIdx.y;
    int b = blockIdx.z;
    int g = h >> 2;
    int tid = threadIdx.x;
    int qrow = qt * 128 + tid;
    size_t t = (size_t)b * NS + qrow;

    unsigned long long q2[32], o2[32];
    const float4* qp = (const float4*)(g_qkv + t * QKVN + h * DH);
    #pragma unroll
    for (int i = 0; i < 16; i++) {
        float4 v = qp[i];
        q2[2*i]   = pk2(v.x * 0.125f, v.y * 0.125f);
        q2[2*i+1] = pk2(v.z * 0.125f, v.w * 0.125f);
        o2[2*i] = 0ULL;
        o2[2*i+1] = 0ULL;
    }
    float m = -INFINITY, l = 0.f;

    __shared__ float4 Ks[32][16];
    __shared__ float4 Vs[32][16];

    int ktmax = (qt * 128 + 127) >> 5;
    for (int kt = 0; kt <= ktmax; kt++) {
        __syncthreads();
        #pragma unroll
        for (int i = 0; i < 4; i++) {
            int f = tid + i * 128;
            int r = f >> 4;
            int c = f & 15;
            size_t krow = (size_t)b * NS + kt * 32 + r;
            Ks[r][c] = ((const float4*)(g_qkv + krow * QKVN + 1024 + g * DH))[c];
            Vs[r][c] = ((const float4*)(g_qkv + krow * QKVN + 1280 + g * DH))[c];
        }
        __syncthreads();

        float s[32];
        int kbase = kt * 32;
        #pragma unroll
        for (int j = 0; j < 32; j++) {
            const ull2_t* kr = (const ull2_t*)Ks[j];
            unsigned long long acc2 = 0ULL;
            #pragma unroll
            for (int c = 0; c < 16; c++) {
                ull2_t kv = kr[c];
                acc2 = fma2(q2[2*c], kv.x, acc2);
                acc2 = fma2(q2[2*c+1], kv.y, acc2);
            }
            float a0, a1;
            upk2(acc2, &a0, &a1);
            s[j] = (kbase + j <= qrow) ? (a0 + a1) : -1e9f;
        }
        float mt = m;
        #pragma unroll
        for (int j = 0; j < 32; j++) mt = fmaxf(mt, s[j]);
        float scalef = __expf(m - mt);
        l *= scalef;
        unsigned long long sc2 = pk2(scalef, scalef);
        #pragma unroll
        for (int i = 0; i < 32; i++) o2[i] = mul2(o2[i], sc2);
        #pragma unroll
        for (int j = 0; j < 32; j++) {
            float p = __expf(s[j] - mt);
            l += p;
            unsigned long long p2 = pk2(p, p);
            const ull2_t* vr = (const ull2_t*)Vs[j];
            #pragma unroll
            for (int c = 0; c < 16; c++) {
                ull2_t vv = vr[c];
                o2[2*c]   = fma2(p2, vv.x, o2[2*c]);
                o2[2*c+1] = fma2(p2, vv.y, o2[2*c+1]);
            }
        }
        m = mt;
    }
    float inv = 1.0f / l;
    uint32_t* oh = (uint32_t*)(g_atth + t * NHID + h * DH);
    uint32_t* ol = (uint32_t*)(g_attl + t * NHID + h * DH);
    #pragma unroll
    for (int i = 0; i < 16; i++) {
        float a0, a1, a2, a3;
        upk2(o2[2*i], &a0, &a1);
        upk2(o2[2*i+1], &a2, &a3);
        a0 *= inv; a1 *= inv; a2 *= inv; a3 *= inv;
        uint32_t l0, l1;
        uint32_t h0 = pack_hi2(a0, a1, &l0);
        uint32_t h1 = pack_hi2(a2, a3, &l1);
        oh[i*2]   = h0;
        oh[i*2+1] = h1;
        ol[i*2]   = l0;
        ol[i*2+1] = l1;
    }
}

// ---------------- router (reads g_xn) ----------------
__global__ void router_k(const float* __restrict__ Wgate) {
    int t = blockIdx.x;
    float acc[NE];
    #pragma unroll
    for (int e = 0; e < NE; e++) acc[e] = 0.f;
    for (int h = threadIdx.x; h < NHID; h += 128) {
        float xv = g_xn[(size_t)t * NHID + h];
        const float4* wr = (const float4*)(Wgate + (size_t)h * NE);
        float4 w0 = wr[0];
        float4 w1 = wr[1];
        acc[0] += xv*w0.x; acc[1] += xv*w0.y; acc[2] += xv*w0.z; acc[3] += xv*w0.w;
        acc[4] += xv*w1.x; acc[5] += xv*w1.y; acc[6] += xv*w1.z; acc[7] += xv*w1.w;
    }
    #pragma unroll
    for (int e = 0; e < NE; e++) {
        #pragma unroll
        for (int o = 16; o; o >>= 1) acc[e] += __shfl_down_sync(0xffffffffu, acc[e], o);
    }
    __shared__ float sm[4][NE];
    int warp = threadIdx.x >> 5;
    int lane = threadIdx.x & 31;
    if (lane == 0) {
        for (int e = 0; e < NE; e++) sm[warp][e] = acc[e];
    }
    __syncthreads();
    if (threadIdx.x == 0) {
        float lg[NE];
        float mx = -INFINITY;
        for (int e = 0; e < NE; e++) {
            lg[e] = sm[0][e] + sm[1][e] + sm[2][e] + sm[3][e];
            mx = fmaxf(mx, lg[e]);
        }
        float p[NE];
        float sum = 0.f;
        for (int e = 0; e < NE; e++) { p[e] = expf(lg[e] - mx); sum += p[e]; }
        float inv = 1.0f / sum;
        for (int e = 0; e < NE; e++) p[e] *= inv;
        int i1 = 0;
        float b1 = p[0];
        for (int e = 1; e < NE; e++) {
            if (p[e] > b1) { b1 = p[e]; i1 = e; }
        }
        int i2 = -1;
        float b2 = -INFINITY;
        for (int e = 0; e < NE; e++) {
            if (e != i1 && p[e] > b2) { b2 = p[e]; i2 = e; }
        }
        int s1 = atomicAdd(&g_cnt[i1], 1);
        g_tok[i1 * NTOK + s1] = t;
        g_wgt[i1 * NTOK + s1] = b1;
        int s2 = atomicAdd(&g_cnt[i2], 1);
        g_tok[i2 * NTOK + s2] = t;
        g_wgt[i2 * NTOK + s2] = b2;
    }
}

__global__ void zero_cnt_k() {
    if (threadIdx.x < NE) g_cnt[threadIdx.x] = 0;
}

// silu(gate)*up from packed g_GU[slot][4096] -> split bf16 g_Gh/g_Gl [slot][2048]
__global__ void silu_k() {
    int slot = blockIdx.x;
    int e = blockIdx.y;
    if (slot >= g_cnt[e]) return;
    size_t b  = ((size_t)e * NTOK + slot) * GUN;
    size_t ob = ((size_t)e * NTOK + slot) * NF;
    for (int f = threadIdx.x * 4; f < NF; f += 1024) {
        float4 g4 = *(const float4*)(g_GU + b + f);
        float4 u4 = *(const float4*)(g_GU + b + NF + f);
        float a0 = g4.x / (1.f + __expf(-g4.x)) * u4.x;
        float a1 = g4.y / (1.f + __expf(-g4.y)) * u4.y;
        float a2 = g4.z / (1.f + __expf(-g4.z)) * u4.z;
        float a3 = g4.w / (1.f + __expf(-g4.w)) * u4.w;
        uint32_t l0, l1;
        uint32_t h0 = pack_hi2(a0, a1, &l0);
        uint32_t h1 = pack_hi2(a2, a3, &l1);
        uint32_t* ph = (uint32_t*)(g_Gh + ob + f);
        uint32_t* pl = (uint32_t*)(g_Gl + ob + f);
        ph[0] = h0;
        ph[1] = h1;
        pl[0] = l0;
        pl[1] = l1;
    }
}

// out = g_h (residual base for down-proj scatter)
__global__ void copy_k(float* __restrict__ dst) {
    size_t i = (size_t)blockIdx.x * 256 + threadIdx.x;
    ((float4*)dst)[i] = ((const float4*)g_h)[i];
}

// ---------------- launch ----------------
extern "C" void kernel_launch(void* const* d_in, const int* in_sizes, int n_in,
                              void* d_out, int out_size) {
    (void)in_sizes; (void)n_in; (void)out_size;
    const float* x     = (const float*)d_in[0];
    const float* w_ln1 = (const float*)d_in[2];
    const float* w_ln2 = (const float*)d_in[3];
    const float* Wq    = (const float*)d_in[4];
    const float* Wk    = (const float*)d_in[5];
    const float* Wv    = (const float*)d_in[6];
    const float* Wo    = (const float*)d_in[7];
    const float* Wgate = (const float*)d_in[8];
    const float* Wg    = (const float*)d_in[9];
    const float* Wu    = (const float*)d_in[10];
    const float* Wd    = (const float*)d_in[11];
    float* out = (float*)d_out;

    cudaFuncSetAttribute(tgemm_k, cudaFuncAttributeMaxDynamicSharedMemorySize, TG_SMEM);

    // 0) ln1 (fused split)
    rmsnorm_split_k<<<NTOK, 256>>>(x, w_ln1, 0, 0);
    // 1) fused QKV weight split-pack
    split_pack_qkv_k<<<NHID*QKVN/4/256, 256>>>((const float4*)Wq, (const float4*)Wk, (const float4*)Wv);
    // 2) fused QKV projection
    tgemm_k<<<dim3(QKVN/128, NTOK/128), 256, TG_SMEM>>>(0, 0, 0);
    // 3) attention  <-- profiled slot
    flash_k<<<dim3(NS/128, NHEADS, NB), 128>>>();
    // 4) Wo split
    split_k<<<NHID*NHID/4/256, 256>>>((const float4*)Wo, NHID*NHID/4, 1);
    // 5) output proj + residual
    tgemm_k<<<dim3(NHID/128, NTOK/128), 256, TG_SMEM>>>(1, x, 0);
    // 6) ln2 (fused split + fp32 for router)
    rmsnorm_split_k<<<NTOK, 256>>>(0, w_ln2, 1, 1);
    // 7) routing
    zero_cnt_k<<<1, 32>>>();
    router_k<<<NTOK, 128>>>(Wgate);
    // 8) MoE weight splits
    split_pack_k<<<NE*NHID*NF/4/256, 256>>>((const float4*)Wg, NE*NHID*NF/4, NF, GUN, 0);
    split_pack_k<<<NE*NHID*NF/4/256, 256>>>((const float4*)Wu, NE*NHID*NF/4, NF, GUN, NF);
    // 9) fused gate|up grouped GEMM
    tgemm_k<<<dim3(GUN/128, NTOK/128, NE), 256, TG_SMEM>>>(2, 0, 0);
    // 10) silu * up -> split
    silu_k<<<dim3(NTOK, NE), 256>>>();
    // 11) Wd split
    split_k<<<NE*NF*NHID/4/256, 256>>>((const float4*)Wd, NE*NF*NHID/4, 3);
    // 12) residual copy + down-proj scatter
    copy_k<<<NTOK, 256>>>(out);
    tgemm_k<<<dim3(NHID/128, NTOK/128, NE), 256, TG_SMEM>>>(3, 0, out);
}